// round 1
// baseline (speedup 1.0000x reference)
#include <cuda_runtime.h>
#include <mma.h>
#include <cstdint>

using namespace nvcuda;

namespace {
constexpr int E_TOT   = 100000;
constexpr int EMB     = 64;
constexpr int HDIM    = 128;
constexpr int MUL     = 64;
constexpr int M_TILE  = 64;
constexpr int THREADS = 256;

// shared-memory leading dims (floats), +8 padding to de-conflict banks
constexpr int LDA = 72;    // emb tile 64 x 64
constexpr int LDH = 136;   // h tile 64 x 128
constexpr int LDB = 168;   // weight staging up to 128 x 160
constexpr int LDW = 328;   // w tile 64 x 320

constexpr int OFF_A = 0;
constexpr int OFF_H = OFF_A + M_TILE * LDA;     // 4608
constexpr int OFF_B = OFF_H + M_TILE * LDH;     // 13312
constexpr int OFF_W = OFF_B + HDIM * LDB;       // 34816
constexpr int SMEM_FLOATS = OFF_W + M_TILE * LDW; // 55808
constexpr int SMEM_BYTES  = SMEM_FLOATS * 4;      // 223232 B
}

__device__ __forceinline__ float rtf32(float x) {
    uint32_t u;
    asm("cvt.rna.tf32.f32 %0, %1;" : "=r"(u) : "f"(x));
    return __uint_as_float(u);
}
__device__ __forceinline__ float silu_f(float x) {
    return x / (1.0f + __expf(-x));
}

using FragA = wmma::fragment<wmma::matrix_a, 16, 16, 8, wmma::precision::tf32, wmma::row_major>;
using FragB = wmma::fragment<wmma::matrix_b, 16, 16, 8, wmma::precision::tf32, wmma::row_major>;
using FragC = wmma::fragment<wmma::accumulator, 16, 16, 8, float>;

__global__ void __launch_bounds__(THREADS, 1)
tpmlp_kernel(const float* __restrict__ emb, const float* __restrict__ x1,
             const float* __restrict__ x2, const float* __restrict__ W0,
             const float* __restrict__ W1,
             const float* __restrict__ P1, const float* __restrict__ P2,
             const float* __restrict__ P3, const float* __restrict__ P4,
             const float* __restrict__ P5, float* __restrict__ out)
{
    extern __shared__ float smem[];
    float* sA = smem + OFF_A;
    float* sH = smem + OFF_H;
    float* sB = smem + OFF_B;
    float* sW = smem + OFF_W;

    const int tid  = threadIdx.x;
    const int warp = tid >> 5;
    const int rt   = warp >> 1;   // row tile 0..3 (16 rows each)
    const int nh   = warp & 1;    // n-half within row tile
    const long row0 = (long)blockIdx.x * M_TILE;

    // ---------------- stage emb tile (zero-padded) + W0, tf32-rounded ----------------
    for (int idx = tid; idx < M_TILE * (EMB / 4); idx += THREADS) {
        int r  = idx >> 4;        // EMB/4 == 16
        int c4 = idx & 15;
        float4 v = make_float4(0.f, 0.f, 0.f, 0.f);
        long g = row0 + r;
        if (g < E_TOT) v = reinterpret_cast<const float4*>(emb + g * EMB)[c4];
        float* d = sA + r * LDA + c4 * 4;
        d[0] = rtf32(v.x); d[1] = rtf32(v.y); d[2] = rtf32(v.z); d[3] = rtf32(v.w);
    }
    for (int idx = tid; idx < EMB * (HDIM / 4); idx += THREADS) {
        int r  = idx >> 5;        // HDIM/4 == 32
        int c4 = idx & 31;
        float4 v = reinterpret_cast<const float4*>(W0 + r * HDIM)[c4];
        float* d = sB + r * LDB + c4 * 4;
        d[0] = rtf32(v.x); d[1] = rtf32(v.y); d[2] = rtf32(v.z); d[3] = rtf32(v.w);
    }
    __syncthreads();

    // ---------------- GEMM1: h1 = silu(emb @ W0 / 8) ----------------
    {
        FragC acc[4];
        #pragma unroll
        for (int n = 0; n < 4; n++) wmma::fill_fragment(acc[n], 0.0f);
        #pragma unroll
        for (int k = 0; k < EMB; k += 8) {
            FragA a;
            wmma::load_matrix_sync(a, sA + rt * 16 * LDA + k, LDA);
            #pragma unroll
            for (int n = 0; n < 4; n++) {
                FragB b;
                wmma::load_matrix_sync(b, sB + k * LDB + (nh * 4 + n) * 16, LDB);
                wmma::mma_sync(acc[n], a, b, acc[n]);
            }
        }
        const float s1 = 0.125f;  // 1/sqrt(64)
        #pragma unroll
        for (int n = 0; n < 4; n++) {
            #pragma unroll
            for (int i = 0; i < acc[n].num_elements; i++)
                acc[n].x[i] = rtf32(silu_f(acc[n].x[i] * s1));
            wmma::store_matrix_sync(sH + rt * 16 * LDH + (nh * 4 + n) * 16,
                                    acc[n], LDH, wmma::mem_row_major);
        }
    }
    __syncthreads();

    // ---------------- stage W1 ----------------
    for (int idx = tid; idx < HDIM * (HDIM / 4); idx += THREADS) {
        int r  = idx >> 5;
        int c4 = idx & 31;
        float4 v = reinterpret_cast<const float4*>(W1 + r * HDIM)[c4];
        float* d = sB + r * LDB + c4 * 4;
        d[0] = rtf32(v.x); d[1] = rtf32(v.y); d[2] = rtf32(v.z); d[3] = rtf32(v.w);
    }
    __syncthreads();

    // ---------------- GEMM2: h2 = silu(h1 @ W1 / sqrt(128)) ----------------
    {
        FragC acc[4];
        #pragma unroll
        for (int n = 0; n < 4; n++) wmma::fill_fragment(acc[n], 0.0f);
        #pragma unroll
        for (int k = 0; k < HDIM; k += 8) {
            FragA a;
            wmma::load_matrix_sync(a, sH + rt * 16 * LDH + k, LDH);
            #pragma unroll
            for (int n = 0; n < 4; n++) {
                FragB b;
                wmma::load_matrix_sync(b, sB + k * LDB + (nh * 4 + n) * 16, LDB);
                wmma::mma_sync(acc[n], a, b, acc[n]);
            }
        }
        __syncthreads();   // everyone done READING sH before we overwrite it
        const float s2 = 0.088388347648318447f;  // 1/sqrt(128)
        #pragma unroll
        for (int n = 0; n < 4; n++) {
            #pragma unroll
            for (int i = 0; i < acc[n].num_elements; i++)
                acc[n].x[i] = rtf32(silu_f(acc[n].x[i] * s2));
            wmma::store_matrix_sync(sH + rt * 16 * LDH + (nh * 4 + n) * 16,
                                    acc[n], LDH, wmma::mem_row_major);
        }
    }
    __syncthreads();

    // ---------------- GEMM3: w = h2 @ [P1..P5] / sqrt(128), in two 160-col chunks ----------------
    const float inv = 0.088388347648318447f;
    const float* Ps[5] = {P1, P2, P3, P4, P5};
    for (int ch = 0; ch < 2; ch++) {
        for (int idx = tid; idx < HDIM * 40; idx += THREADS) {
            int r  = idx / 40;
            int c4 = idx % 40;
            int cg = ch * 160 + c4 * 4;      // global w-column (0..319), i*64+u layout
            int pi = cg >> 6;
            int u  = cg & 63;
            float4 v = reinterpret_cast<const float4*>(Ps[pi] + r * MUL)[u >> 2];
            float* d = sB + r * LDB + c4 * 4;
            d[0] = rtf32(v.x); d[1] = rtf32(v.y); d[2] = rtf32(v.z); d[3] = rtf32(v.w);
        }
        __syncthreads();

        FragC acc[5];
        #pragma unroll
        for (int n = 0; n < 5; n++) wmma::fill_fragment(acc[n], 0.0f);
        #pragma unroll
        for (int k = 0; k < HDIM; k += 8) {
            FragA a;
            wmma::load_matrix_sync(a, sH + rt * 16 * LDH + k, LDH);
            #pragma unroll
            for (int n = 0; n < 5; n++) {
                FragB b;
                wmma::load_matrix_sync(b, sB + k * LDB + (nh * 5 + n) * 16, LDB);
                wmma::mma_sync(acc[n], a, b, acc[n]);
            }
        }
        #pragma unroll
        for (int n = 0; n < 5; n++) {
            #pragma unroll
            for (int i = 0; i < acc[n].num_elements; i++) acc[n].x[i] *= inv;
            wmma::store_matrix_sync(sW + rt * 16 * LDW + ch * 160 + (nh * 5 + n) * 16,
                                    acc[n], LDW, wmma::mem_row_major);
        }
        __syncthreads();  // also gates sB re-staging on next chunk
    }

    // ---------------- epilogue: equivariant tensor product, pure fp32 ----------------
    const float INV_SQRT2 = 0.70710678118654752f;
    const float INV_SQRT3 = 0.57735026918962576f;
    const float INV_SQRT6 = 0.40824829046386302f;

    for (int idx = tid; idx < M_TILE * MUL; idx += THREADS) {
        int r = idx >> 6;
        int u = idx & 63;
        long g = row0 + r;
        if (g >= E_TOT) continue;

        const float* x1r = x1 + g * 256;
        float x10 = x1r[u];
        float a0 = x1r[64 + 3 * u + 0];
        float a1 = x1r[64 + 3 * u + 1];
        float a2 = x1r[64 + 3 * u + 2];
        const float* x2r = x2 + g * 4;
        float b0 = x2r[0], c0 = x2r[1], c1 = x2r[2], c2 = x2r[3];

        const float* wr = sW + r * LDW;
        float w1 = wr[u];
        float w2 = wr[64 + u];
        float w3 = wr[128 + u];
        float w4 = wr[192 + u];
        float w5 = wr[256 + u];

        float* o = out + g * 448;
        float dot = a0 * c0 + a1 * c1 + a2 * c2;

        o[u] = INV_SQRT2 * (w1 * x10 * b0 + w4 * dot * INV_SQRT3);

        o[64 + 3 * u + 0] = INV_SQRT2 * (w2 * a0 * b0 + w3 * x10 * c0);
        o[64 + 3 * u + 1] = INV_SQRT2 * (w2 * a1 * b0 + w3 * x10 * c1);
        o[64 + 3 * u + 2] = INV_SQRT2 * (w2 * a2 * b0 + w3 * x10 * c2);

        float r0 = a1 * c2 - a2 * c1;
        float r1 = a2 * c0 - a0 * c2;
        float r2 = a0 * c1 - a1 * c0;
        o[256 + 3 * u + 0] = w5 * r0 * INV_SQRT6;
        o[256 + 3 * u + 1] = w5 * r1 * INV_SQRT6;
        o[256 + 3 * u + 2] = w5 * r2 * INV_SQRT6;
    }
}

extern "C" void kernel_launch(void* const* d_in, const int* in_sizes, int n_in,
                              void* d_out, int out_size) {
    (void)in_sizes; (void)n_in; (void)out_size;
    const float* emb = (const float*)d_in[0];
    const float* x1  = (const float*)d_in[1];
    const float* x2  = (const float*)d_in[2];
    const float* W0  = (const float*)d_in[3];
    const float* W1  = (const float*)d_in[4];
    const float* P1  = (const float*)d_in[5];
    const float* P2  = (const float*)d_in[6];
    const float* P3  = (const float*)d_in[7];
    const float* P4  = (const float*)d_in[8];
    const float* P5  = (const float*)d_in[9];
    float* out = (float*)d_out;

    cudaFuncSetAttribute(tpmlp_kernel,
                         cudaFuncAttributeMaxDynamicSharedMemorySize, SMEM_BYTES);

    int grid = (E_TOT + M_TILE - 1) / M_TILE;  // 1563
    tpmlp_kernel<<<grid, THREADS, SMEM_BYTES>>>(emb, x1, x2, W0, W1,
                                                P1, P2, P3, P4, P5, out);
}

// round 3
// speedup vs baseline: 1.4592x; 1.4592x over previous
#include <cuda_runtime.h>
#include <mma.h>
#include <cstdint>

using namespace nvcuda;

namespace {
constexpr int E_TOT   = 100000;
constexpr int MT      = 64;
constexpr int THREADS = 256;

constexpr int LDH  = 136;  // h tile 64 x 128
constexpr int LDA  = 72;   // emb tile 64 x 64
constexpr int LDB1 = 136;  // W0 64 x 128
constexpr int LDB2 = 72;   // W1 half 128 x 64
constexpr int LDB3 = 88;   // P chunk 128 x 80
constexpr int LDW  = 88;   // w chunk 64 x 80

constexpr int OFF_H = 0;                   // 64*136      = 8704 floats
constexpr int OFF_B = OFF_H + 64 * LDH;    // staging max = 128*88 = 11264 floats
constexpr int OFF_X = OFF_B + 128 * LDB3;  // union(A 64*72, W 64*88) = 5632 floats
constexpr int SMEM_FLOATS = OFF_X + 64 * LDW;   // 25600
constexpr int SMEM_BYTES  = SMEM_FLOATS * 4;    // 102400 -> 2 CTAs/SM
}

__device__ __forceinline__ float rtf32(float x) {
    uint32_t u;
    asm("cvt.rna.tf32.f32 %0, %1;" : "=r"(u) : "f"(x));
    return __uint_as_float(u);
}
__device__ __forceinline__ float silu_f(float x) {
    return x / (1.0f + __expf(-x));
}

using FragA = wmma::fragment<wmma::matrix_a, 16, 16, 8, wmma::precision::tf32, wmma::row_major>;
using FragB = wmma::fragment<wmma::matrix_b, 16, 16, 8, wmma::precision::tf32, wmma::row_major>;
using FragC = wmma::fragment<wmma::accumulator, 16, 16, 8, float>;

__global__ void __launch_bounds__(THREADS, 2)
tpmlp_kernel(const float* __restrict__ emb, const float* __restrict__ x1,
             const float* __restrict__ x2, const float* __restrict__ W0,
             const float* __restrict__ W1,
             const float* __restrict__ P1, const float* __restrict__ P2,
             const float* __restrict__ P3, const float* __restrict__ P4,
             const float* __restrict__ P5, float* __restrict__ out)
{
    extern __shared__ float sm[];
    float* sH = sm + OFF_H;
    float* sB = sm + OFF_B;
    float* sX = sm + OFF_X;     // emb tile, later w chunk

    const int tid  = threadIdx.x;
    const int warp = tid >> 5;
    const int lane = tid & 31;  (void)lane;
    const int rt   = warp & 3;      // row tile (16 rows)
    const int nh   = warp >> 2;     // n-group
    const long row0 = (long)blockIdx.x * MT;

    // ---------------- stage emb tile (zero-padded) + W0, tf32 ----------------
    for (int idx = tid; idx < MT * 16; idx += THREADS) {
        int r  = idx >> 4;
        int c4 = (idx & 15) * 4;
        float4 v = make_float4(0.f, 0.f, 0.f, 0.f);
        long g = row0 + r;
        if (g < E_TOT) v = *(const float4*)(emb + g * 64 + c4);
        float* d = sX + r * LDA + c4;
        d[0] = rtf32(v.x); d[1] = rtf32(v.y); d[2] = rtf32(v.z); d[3] = rtf32(v.w);
    }
    for (int idx = tid; idx < 64 * 32; idx += THREADS) {
        int k  = idx >> 5;
        int c4 = (idx & 31) * 4;
        float4 v = *(const float4*)(W0 + k * 128 + c4);
        float* d = sB + k * LDB1 + c4;
        d[0] = rtf32(v.x); d[1] = rtf32(v.y); d[2] = rtf32(v.z); d[3] = rtf32(v.w);
    }
    __syncthreads();

    // ---------------- GEMM1: h1 = silu(emb @ W0 / 8) ----------------
    {
        FragC acc[4];
        #pragma unroll
        for (int n = 0; n < 4; n++) wmma::fill_fragment(acc[n], 0.0f);
        #pragma unroll
        for (int k = 0; k < 64; k += 8) {
            FragA a;
            wmma::load_matrix_sync(a, sX + rt * 16 * LDA + k, LDA);
            #pragma unroll
            for (int n = 0; n < 4; n++) {
                FragB b;
                wmma::load_matrix_sync(b, sB + k * LDB1 + nh * 64 + n * 16, LDB1);
                wmma::mma_sync(acc[n], a, b, acc[n]);
            }
        }
        const float s1 = 0.125f;
        #pragma unroll
        for (int n = 0; n < 4; n++) {
            #pragma unroll
            for (int i = 0; i < acc[n].num_elements; i++)
                acc[n].x[i] = rtf32(silu_f(acc[n].x[i] * s1));
            wmma::store_matrix_sync(sH + rt * 16 * LDH + nh * 64 + n * 16,
                                    acc[n], LDH, wmma::mem_row_major);
        }
    }
    __syncthreads();

    // ---------------- GEMM2: h2 = silu(h1 @ W1 / sqrt(128)) * inv ----------------
    {
        FragC acc[2][2];
        #pragma unroll
        for (int h = 0; h < 2; h++) {
            // stage W1 half h: [128k x 64n]
            for (int idx = tid; idx < 128 * 16; idx += THREADS) {
                int k  = idx >> 4;
                int c4 = (idx & 15) * 4;
                float4 v = *(const float4*)(W1 + k * 128 + h * 64 + c4);
                float* d = sB + k * LDB2 + c4;
                d[0] = rtf32(v.x); d[1] = rtf32(v.y); d[2] = rtf32(v.z); d[3] = rtf32(v.w);
            }
            __syncthreads();
            #pragma unroll
            for (int t = 0; t < 2; t++) wmma::fill_fragment(acc[h][t], 0.0f);
            #pragma unroll
            for (int k = 0; k < 128; k += 8) {
                FragA a;
                wmma::load_matrix_sync(a, sH + rt * 16 * LDH + k, LDH);
                #pragma unroll
                for (int t = 0; t < 2; t++) {
                    FragB b;
                    wmma::load_matrix_sync(b, sB + k * LDB2 + (nh * 2 + t) * 16, LDB2);
                    wmma::mma_sync(acc[h][t], a, b, acc[h][t]);
                }
            }
            __syncthreads();   // h=0: before restage; h=1: before sH overwrite
        }
        const float s2  = 0.08838834764831845f;   // 1/sqrt(128)
        const float inv = 0.08838834764831845f;   // folded P-scale
        #pragma unroll
        for (int h = 0; h < 2; h++) {
            #pragma unroll
            for (int t = 0; t < 2; t++) {
                #pragma unroll
                for (int i = 0; i < acc[h][t].num_elements; i++)
                    acc[h][t].x[i] = rtf32(silu_f(acc[h][t].x[i] * s2) * inv);
                wmma::store_matrix_sync(sH + rt * 16 * LDH + h * 64 + (nh * 2 + t) * 16,
                                        acc[h][t], LDH, wmma::mem_row_major);
            }
        }
    }
    __syncthreads();

    // ---------------- GEMM3 + epilogue in 4 chunks of 16 u-values ----------------
    const float* Ps[5] = {P1, P2, P3, P4, P5};
    const float INV_SQRT2 = 0.7071067811865476f;
    const float INV_SQRT3 = 0.5773502691896258f;
    const float INV_SQRT6 = 0.4082482904638631f;

    const int nb   = (nh == 0) ? 0 : 3;   // n-tile base within chunk
    const int ncnt = (nh == 0) ? 3 : 2;

    for (int c = 0; c < 4; c++) {
        // stage P chunk: col j = p*16 + uu  ->  Ps[p][k][c*16+uu], [128k x 80n]
        for (int idx = tid; idx < 128 * 20; idx += THREADS) {
            int k  = idx / 20;
            int jj = idx % 20;
            int p  = jj >> 2;
            int q  = (jj & 3) * 4;
            float4 v = *(const float4*)(Ps[p] + k * 64 + c * 16 + q);
            float* d = sB + k * LDB3 + p * 16 + q;
            d[0] = rtf32(v.x); d[1] = rtf32(v.y); d[2] = rtf32(v.z); d[3] = rtf32(v.w);
        }
        __syncthreads();

        FragC acc[3];
        for (int t = 0; t < ncnt; t++) wmma::fill_fragment(acc[t], 0.0f);
        #pragma unroll
        for (int k = 0; k < 128; k += 8) {
            FragA a;
            wmma::load_matrix_sync(a, sH + rt * 16 * LDH + k, LDH);
            for (int t = 0; t < ncnt; t++) {
                FragB b;
                wmma::load_matrix_sync(b, sB + k * LDB3 + (nb + t) * 16, LDB3);
                wmma::mma_sync(acc[t], a, b, acc[t]);
            }
        }
        for (int t = 0; t < ncnt; t++)
            wmma::store_matrix_sync(sX + rt * 16 * LDW + (nb + t) * 16,
                                    acc[t], LDW, wmma::mem_row_major);
        __syncthreads();

        // epilogue for u in [c*16, c*16+16)
        for (int idx = tid; idx < MT * 16; idx += THREADS) {
            int r  = idx >> 4;
            int uu = idx & 15;
            long g = row0 + r;
            if (g >= E_TOT) continue;
            int u = c * 16 + uu;

            const float* x1r = x1 + g * 256;
            float x10 = x1r[u];
            float a0 = x1r[64 + 3 * u + 0];
            float a1 = x1r[64 + 3 * u + 1];
            float a2 = x1r[64 + 3 * u + 2];
            float4 t2 = *(const float4*)(x2 + g * 4);
            float b0 = t2.x, c0 = t2.y, c1 = t2.z, c2 = t2.w;

            const float* wr = sX + r * LDW;
            float w1 = wr[uu];
            float w2 = wr[16 + uu];
            float w3 = wr[32 + uu];
            float w4 = wr[48 + uu];
            float w5 = wr[64 + uu];

            float* o = out + g * 448;
            float dot = a0 * c0 + a1 * c1 + a2 * c2;

            o[u] = INV_SQRT2 * (w1 * x10 * b0 + w4 * dot * INV_SQRT3);

            o[64 + 3 * u + 0] = INV_SQRT2 * (w2 * a0 * b0 + w3 * x10 * c0);
            o[64 + 3 * u + 1] = INV_SQRT2 * (w2 * a1 * b0 + w3 * x10 * c1);
            o[64 + 3 * u + 2] = INV_SQRT2 * (w2 * a2 * b0 + w3 * x10 * c2);

            float r0 = a1 * c2 - a2 * c1;
            float r1 = a2 * c0 - a0 * c2;
            float r2 = a0 * c1 - a1 * c0;
            o[256 + 3 * u + 0] = w5 * r0 * INV_SQRT6;
            o[256 + 3 * u + 1] = w5 * r1 * INV_SQRT6;
            o[256 + 3 * u + 2] = w5 * r2 * INV_SQRT6;
        }
        __syncthreads();   // before next chunk's restage of sB / sX
    }
}

extern "C" void kernel_launch(void* const* d_in, const int* in_sizes, int n_in,
                              void* d_out, int out_size) {
    (void)in_sizes; (void)n_in; (void)out_size;
    const float* emb = (const float*)d_in[0];
    const float* x1  = (const float*)d_in[1];
    const float* x2  = (const float*)d_in[2];
    const float* W0  = (const float*)d_in[3];
    const float* W1  = (const float*)d_in[4];
    const float* P1  = (const float*)d_in[5];
    const float* P2  = (const float*)d_in[6];
    const float* P3  = (const float*)d_in[7];
    const float* P4  = (const float*)d_in[8];
    const float* P5  = (const float*)d_in[9];
    float* out = (float*)d_out;

    cudaFuncSetAttribute(tpmlp_kernel,
                         cudaFuncAttributeMaxDynamicSharedMemorySize, SMEM_BYTES);

    int grid = (E_TOT + MT - 1) / MT;   // 1563
    tpmlp_kernel<<<grid, THREADS, SMEM_BYTES>>>(emb, x1, x2, W0, W1,
                                                P1, P2, P3, P4, P5, out);
}

// round 5
// speedup vs baseline: 1.4937x; 1.0236x over previous
#include <cuda_runtime.h>
#include <mma.h>
#include <cstdint>

using namespace nvcuda;

namespace {
constexpr int E_TOT = 100000;
constexpr int NSM   = 152;          // GB300 SM count

// ---------------- K1 ----------------
constexpr int K1_MT      = 64;
constexpr int K1_TILES   = (E_TOT + K1_MT - 1) / K1_MT;   // 1563
constexpr int K1_THREADS = 512;
constexpr int LDW0 = 132, LDW1 = 132, LDH = 132, LDE = 68;
constexpr int O_W0 = 0;
constexpr int O_W1 = O_W0 + 64 * LDW0;      // 8448
constexpr int O_H  = O_W1 + 128 * LDW1;     // 25344
constexpr int O_E  = O_H + 64 * LDH;        // 33792
constexpr int K1_SMEM_B = (O_E + 64 * LDE) * 4;   // 152576

// ---------------- K2 ----------------
constexpr int K2_MT      = 32;
constexpr int K2_TILES   = E_TOT / K2_MT;   // 3125 (exact)
constexpr int K2_THREADS = 512;
constexpr int LDP = 164, LDH2 = 132, LDX = 164;
constexpr int O_P = 0;                       // 2 chunks * 128 * 164
constexpr int O_R = O_P + 2 * 128 * LDP;     // 41984 : ring 2 * 32*132
constexpr int O_X = O_R + 2 * 32 * LDH2;     // 50432 : 32*164
constexpr int K2_SMEM_B = (O_X + 32 * LDX) * 4;   // 222720
}

// h2 scratch (tf32-rounded, pre-scaled by 1/sqrt(128)) : 100032 x 128 f32
__device__ float g_h2[(size_t)K1_TILES * K1_MT * 128];

__device__ __forceinline__ float rtf32(float x) {
    uint32_t u;
    asm("cvt.rna.tf32.f32 %0, %1;" : "=r"(u) : "f"(x));
    return __uint_as_float(u);
}
__device__ __forceinline__ float silu_f(float x) {
    return x / (1.0f + __expf(-x));
}
__device__ __forceinline__ uint32_t smem_u32(const void* p) {
    uint32_t a;
    asm("{ .reg .u64 t; cvta.to.shared.u64 t, %1; cvt.u32.u64 %0, t; }"
        : "=r"(a) : "l"(p));
    return a;
}
__device__ __forceinline__ void cpa16(uint32_t d, const void* s) {
    asm volatile("cp.async.cg.shared.global [%0], [%1], 16;" :: "r"(d), "l"(s));
}
__device__ __forceinline__ void cpa_commit() {
    asm volatile("cp.async.commit_group;" ::: "memory");
}
__device__ __forceinline__ void cpa_wait0() {
    asm volatile("cp.async.wait_group 0;" ::: "memory");
}

using FragA = wmma::fragment<wmma::matrix_a, 16, 16, 8, wmma::precision::tf32, wmma::row_major>;
using FragB = wmma::fragment<wmma::matrix_b, 16, 16, 8, wmma::precision::tf32, wmma::row_major>;
using FragC = wmma::fragment<wmma::accumulator, 16, 16, 8, float>;

// ======================= K1: h2 for all rows =======================
__global__ void __launch_bounds__(K1_THREADS, 1)
k1_mlp(const float* __restrict__ emb, const float* __restrict__ W0,
       const float* __restrict__ W1)
{
    extern __shared__ float sm[];
    const int tid  = threadIdx.x;
    const int warp = tid >> 5;
    const int rt   = warp & 3;    // 4 row tiles of 16
    const int ng   = warp >> 2;   // 4 col groups of 32

    // ---- stage W0 [64k x 128n] and W1 [128k x 128n] once, tf32 ----
    for (int q = tid; q < 64 * 32; q += K1_THREADS) {
        int k = q >> 5, c4 = (q & 31) * 4;
        float4 v = *(const float4*)(W0 + k * 128 + c4);
        float* d = sm + O_W0 + k * LDW0 + c4;
        d[0] = rtf32(v.x); d[1] = rtf32(v.y); d[2] = rtf32(v.z); d[3] = rtf32(v.w);
    }
    for (int q = tid; q < 128 * 32; q += K1_THREADS) {
        int k = q >> 5, c4 = (q & 31) * 4;
        float4 v = *(const float4*)(W1 + k * 128 + c4);
        float* d = sm + O_W1 + k * LDW1 + c4;
        d[0] = rtf32(v.x); d[1] = rtf32(v.y); d[2] = rtf32(v.z); d[3] = rtf32(v.w);
    }

    // emb tile register double-buffer: thread covers f4 idx tid and tid+512
    const int q0 = tid, q1 = tid + 512;
    const int r0 = q0 >> 4, c0 = (q0 & 15) * 4;
    const int r1 = q1 >> 4, c1 = (q1 & 15) * 4;
    float4 a0, a1;
    auto load_tile = [&](int t) {
        long g0 = (long)t * K1_MT + r0;
        long g1 = (long)t * K1_MT + r1;
        a0 = (g0 < E_TOT) ? *(const float4*)(emb + g0 * 64 + c0)
                          : make_float4(0.f, 0.f, 0.f, 0.f);
        a1 = (g1 < E_TOT) ? *(const float4*)(emb + g1 * 64 + c1)
                          : make_float4(0.f, 0.f, 0.f, 0.f);
    };
    load_tile(blockIdx.x);

    const float s1  = 0.125f;               // 1/sqrt(64)
    const float s2  = 0.08838834764831845f; // 1/sqrt(128)
    const float inv = 0.08838834764831845f; // folded P-scale

    for (int t = blockIdx.x; t < K1_TILES; t += NSM) {
        // STS current emb tile (tf32), visible after sync
        {
            float* d = sm + O_E + r0 * LDE + c0;
            d[0] = rtf32(a0.x); d[1] = rtf32(a0.y); d[2] = rtf32(a0.z); d[3] = rtf32(a0.w);
            d = sm + O_E + r1 * LDE + c1;
            d[0] = rtf32(a1.x); d[1] = rtf32(a1.y); d[2] = rtf32(a1.z); d[3] = rtf32(a1.w);
        }
        __syncthreads();
        if (t + NSM < K1_TILES) load_tile(t + NSM);   // hide under MMAs

        // ---- GEMM1: h1 = silu(emb @ W0 * s1) ----
        {
            FragC acc[2];
            #pragma unroll
            for (int n = 0; n < 2; n++) wmma::fill_fragment(acc[n], 0.0f);
            #pragma unroll
            for (int k = 0; k < 64; k += 8) {
                FragA a;
                wmma::load_matrix_sync(a, sm + O_E + rt * 16 * LDE + k, LDE);
                #pragma unroll
                for (int n = 0; n < 2; n++) {
                    FragB b;
                    wmma::load_matrix_sync(b, sm + O_W0 + k * LDW0 + ng * 32 + n * 16, LDW0);
                    wmma::mma_sync(acc[n], a, b, acc[n]);
                }
            }
            #pragma unroll
            for (int n = 0; n < 2; n++) {
                #pragma unroll
                for (int i = 0; i < acc[n].num_elements; i++)
                    acc[n].x[i] = rtf32(silu_f(acc[n].x[i] * s1));
                wmma::store_matrix_sync(sm + O_H + rt * 16 * LDH + ng * 32 + n * 16,
                                        acc[n], LDH, wmma::mem_row_major);
            }
        }
        __syncthreads();

        // ---- GEMM2: h2 = silu(h1 @ W1 * s2) * inv, rounded, -> global ----
        {
            FragC acc[2];
            #pragma unroll
            for (int n = 0; n < 2; n++) wmma::fill_fragment(acc[n], 0.0f);
            #pragma unroll
            for (int k = 0; k < 128; k += 8) {
                FragA a;
                wmma::load_matrix_sync(a, sm + O_H + rt * 16 * LDH + k, LDH);
                #pragma unroll
                for (int n = 0; n < 2; n++) {
                    FragB b;
                    wmma::load_matrix_sync(b, sm + O_W1 + k * LDW1 + ng * 32 + n * 16, LDW1);
                    wmma::mma_sync(acc[n], a, b, acc[n]);
                }
            }
            float* h2t = g_h2 + (size_t)t * K1_MT * 128;
            #pragma unroll
            for (int n = 0; n < 2; n++) {
                #pragma unroll
                for (int i = 0; i < acc[n].num_elements; i++)
                    acc[n].x[i] = rtf32(silu_f(acc[n].x[i] * s2) * inv);
                wmma::store_matrix_sync(h2t + rt * 16 * 128 + ng * 32 + n * 16,
                                        acc[n], 128, wmma::mem_row_major);
            }
        }
        __syncthreads();   // before next iter overwrites sEmb / sH
    }
}

// ======================= K2: GEMM3 + tensor-product epilogue =======================
__global__ void __launch_bounds__(K2_THREADS, 1)
k2_tp(const float* __restrict__ x1, const float* __restrict__ x2,
      const float* __restrict__ P1, const float* __restrict__ P2,
      const float* __restrict__ P3, const float* __restrict__ P4,
      const float* __restrict__ P5, float* __restrict__ out)
{
    extern __shared__ float sm[];
    const uint32_t sb = smem_u32(sm);
    const int tid  = threadIdx.x;
    const int warp = tid >> 5;
    const int rt   = warp & 1;    // 2 row tiles of 16 (MT=32)
    const int ng   = warp >> 1;   // 8 n groups

    // cp.async one h2 tile (32 rows x 128 floats = 32 f4/row, 1024 f4 total):
    // thread covers f4 index tid and tid+512.  r = q>>5 (0..31), j4 = (q&31)*4.
    auto issue_tile = [&](int t, int slot) {
        #pragma unroll
        for (int h = 0; h < 2; h++) {
            int q  = tid + h * 512;
            int r  = q >> 5;
            int j4 = (q & 31) * 4;
            const float* src = g_h2 + ((size_t)t * K2_MT + r) * 128 + j4;
            uint32_t dst = sb + (uint32_t)(O_R + slot * 32 * LDH2 + r * LDH2 + j4) * 4;
            cpa16(dst, src);
        }
        cpa_commit();
    };

    // prefetch tile for iter 0 while staging Pcat
    if (blockIdx.x < K2_TILES) issue_tile(blockIdx.x, 0);

    // ---- stage Pcat resident: chunk c (160 cols: p*32+uu <-> u=c*32+uu), tf32 ----
    const float* Ps[5] = {P1, P2, P3, P4, P5};
    for (int q = tid; q < 10240; q += K2_THREADS) {   // 2*128*40 f4
        int c2  = q / 5120;
        int rem = q - c2 * 5120;
        int k   = rem / 40;
        int j4  = (rem % 40) * 4;
        int p   = j4 >> 5, uu = j4 & 31;
        float4 v = *(const float4*)(Ps[p] + k * 64 + c2 * 32 + uu);
        float* d = sm + O_P + c2 * 128 * LDP + k * LDP + j4;
        d[0] = rtf32(v.x); d[1] = rtf32(v.y); d[2] = rtf32(v.z); d[3] = rtf32(v.w);
    }
    cpa_wait0();
    __syncthreads();

    const float INV_SQRT2 = 0.7071067811865476f;
    const float INV_SQRT3 = 0.5773502691896258f;
    const float INV_SQRT6 = 0.4082482904638631f;

    const int ntiles = (ng < 2) ? 2 : 1;

    for (int t = blockIdx.x, it = 0; t < K2_TILES; t += NSM, it++) {
        const int slot = it & 1;
        if (t + NSM < K2_TILES) issue_tile(t + NSM, slot ^ 1);
        const long g0 = (long)t * K2_MT;

        #pragma unroll
        for (int c = 0; c < 2; c++) {
            // ---- chunk MMA: w[:, c-chunk] = h2_tile @ Pcat[c] ----
            FragC acc[2];
            for (int s = 0; s < ntiles; s++) wmma::fill_fragment(acc[s], 0.0f);
            #pragma unroll
            for (int k = 0; k < 128; k += 8) {
                FragA a;
                wmma::load_matrix_sync(a, sm + O_R + slot * 32 * LDH2 + rt * 16 * LDH2 + k, LDH2);
                for (int s = 0; s < ntiles; s++) {
                    int nt = (s == 0) ? ng : 8 + ng;
                    FragB b;
                    wmma::load_matrix_sync(b, sm + O_P + c * 128 * LDP + k * LDP + nt * 16, LDP);
                    wmma::mma_sync(acc[s], a, b, acc[s]);
                }
            }
            for (int s = 0; s < ntiles; s++) {
                int nt = (s == 0) ? ng : 8 + ng;
                wmma::store_matrix_sync(sm + O_X + rt * 16 * LDX + nt * 16,
                                        acc[s], LDX, wmma::mem_row_major);
            }
            __syncthreads();

            // ---- epilogue for u in [c*32, c*32+32) ----
            #pragma unroll
            for (int h = 0; h < 2; h++) {
                int idx = tid + h * 512;            // 1024 tasks
                int r = idx >> 5, uu = idx & 31;
                int u = c * 32 + uu;
                long g = g0 + r;

                const float* x1r = x1 + g * 256;
                float x10 = x1r[u];
                float a0 = x1r[64 + 3 * u + 0];
                float a1 = x1r[64 + 3 * u + 1];
                float a2 = x1r[64 + 3 * u + 2];
                float4 t2 = *(const float4*)(x2 + g * 4);
                float b0 = t2.x, c0v = t2.y, c1v = t2.z, c2v = t2.w;

                const float* wr = sm + O_X + r * LDX;
                float w1 = wr[uu];
                float w2 = wr[32 + uu];
                float w3 = wr[64 + uu];
                float w4 = wr[96 + uu];
                float w5 = wr[128 + uu];

                float* o = out + g * 448;
                float dot = a0 * c0v + a1 * c1v + a2 * c2v;

                o[u] = INV_SQRT2 * (w1 * x10 * b0 + w4 * dot * INV_SQRT3);

                o[64 + 3 * u + 0] = INV_SQRT2 * (w2 * a0 * b0 + w3 * x10 * c0v);
                o[64 + 3 * u + 1] = INV_SQRT2 * (w2 * a1 * b0 + w3 * x10 * c1v);
                o[64 + 3 * u + 2] = INV_SQRT2 * (w2 * a2 * b0 + w3 * x10 * c2v);

                float r0 = a1 * c2v - a2 * c1v;
                float r1 = a2 * c0v - a0 * c2v;
                float r2 = a0 * c1v - a1 * c0v;
                o[256 + 3 * u + 0] = w5 * r0 * INV_SQRT6;
                o[256 + 3 * u + 1] = w5 * r1 * INV_SQRT6;
                o[256 + 3 * u + 2] = w5 * r2 * INV_SQRT6;
            }
            __syncthreads();
        }
        cpa_wait0();      // next tile staged
        __syncthreads();
    }
}

extern "C" void kernel_launch(void* const* d_in, const int* in_sizes, int n_in,
                              void* d_out, int out_size) {
    (void)in_sizes; (void)n_in; (void)out_size;
    const float* emb = (const float*)d_in[0];
    const float* x1  = (const float*)d_in[1];
    const float* x2  = (const float*)d_in[2];
    const float* W0  = (const float*)d_in[3];
    const float* W1  = (const float*)d_in[4];
    const float* P1  = (const float*)d_in[5];
    const float* P2  = (const float*)d_in[6];
    const float* P3  = (const float*)d_in[7];
    const float* P4  = (const float*)d_in[8];
    const float* P5  = (const float*)d_in[9];
    float* out = (float*)d_out;

    cudaFuncSetAttribute(k1_mlp, cudaFuncAttributeMaxDynamicSharedMemorySize, K1_SMEM_B);
    cudaFuncSetAttribute(k2_tp,  cudaFuncAttributeMaxDynamicSharedMemorySize, K2_SMEM_B);

    k1_mlp<<<NSM, K1_THREADS, K1_SMEM_B>>>(emb, W0, W1);
    k2_tp<<<NSM, K2_THREADS, K2_SMEM_B>>>(x1, x2, P1, P2, P3, P4, P5, out);
}